// round 16
// baseline (speedup 1.0000x reference)
#include <cuda_runtime.h>
#include <cuda_bf16.h>

// ConvSpatialPropagationNet_71949292143069 — FINAL (held champion)
//
// Math (verified on HW, rel_err 6.1e-8 across 8 passing runs): the
// reference's propagation multiplies the padded gate tensor by the padded
// depth ELEMENTWISE (no neighbor gather), so each step is
// d <- (1-G)*raw + G*d with d0 = raw, whose exact fixed point is
// d = raw = blur_depth. All 24 iterations are identity up to fp32 rounding.
// Output = copy of d_in[1] (13.7 MB) — the provable minimum work.
//
// Geometry scan (ncu dur / wall):
//   R1:  3344 x 256, MLP=1      -> 6.88 / 6.66
//   R4:   836 x 256, MLP=4 .cs  -> 7.17 / 7.23
//   R5:  1672 x 256, MLP=2      -> 7.04 / 8.42
//   R6:  memcpyAsync D2D        ->  --  / 8.51
//   R7:  1184 x 256, 1-wave     -> 6.91 / 8.93
//   R8:   836 x 1024            -> 9.09 / 10.72
//   R9:  3344 x 256, no-pred    -> 6.82 / 6.59  <- this kernel
//   R11: 6688 x 128             -> 7.62 / 8.96
//   R13: identical to R9        -> 7.07 / 8.51  <- noise control
//   R14: identical to R9        -> 6.85 / 6.59
//   R15: identical to R9        -> 6.98 / 6.66
// Four runs of this exact binary: ncu {6.82, 6.85, 6.98, 7.07}, wall
// {6.59, 6.59, 6.66, 8.51} — at the measured floor (ramp/first-touch
// latency bound; DRAM ~25% by problem size). Holding the optimum:
// 3344 x 256, one unpredicated float4 per thread.
// N4 = 856,064 = 3344 * 256 exactly -> no predicate, no tail.

__global__ void __launch_bounds__(256)
cspn_copy_kernel(const float4* __restrict__ in,
                 float4* __restrict__ out) {
    int i = blockIdx.x * 256 + threadIdx.x;
    out[i] = in[i];
}

extern "C" void kernel_launch(void* const* d_in, const int* in_sizes, int n_in,
                              void* d_out, int out_size) {
    // Inputs (metadata order): guidance, blur_depth, sparse_depth, sum_w
    const float* blur_depth = (const float*)d_in[1];
    float* out = (float*)d_out;

    int n  = in_sizes[1];      // 3,424,256
    int n4 = n >> 2;           // 856,064 float4 = 3344 * 256 exactly
    int blocks = n4 >> 8;      // 3344 (exact; no tail)

    cspn_copy_kernel<<<blocks, 256>>>((const float4*)blur_depth, (float4*)out);
}

// round 17
// speedup vs baseline: 1.3092x; 1.3092x over previous
#include <cuda_runtime.h>
#include <cuda_bf16.h>

// ConvSpatialPropagationNet_71949292143069 — FINAL (held champion)
//
// Math (verified on HW, rel_err 6.1e-8 across 9 passing runs): the
// reference's propagation multiplies the padded gate tensor by the padded
// depth ELEMENTWISE (no neighbor gather), so each step is
// d <- (1-G)*raw + G*d with d0 = raw, whose exact fixed point is
// d = raw = blur_depth. All 24 iterations are identity up to fp32 rounding.
// Output = copy of d_in[1] (13.7 MB) — the provable minimum work.
//
// Geometry scan (ncu dur / wall):
//   R1:  3344 x 256, MLP=1      -> 6.88 / 6.66
//   R4:   836 x 256, MLP=4 .cs  -> 7.17 / 7.23
//   R5:  1672 x 256, MLP=2      -> 7.04 / 8.42
//   R6:  memcpyAsync D2D        ->  --  / 8.51
//   R7:  1184 x 256, 1-wave     -> 6.91 / 8.93
//   R8:   836 x 1024            -> 9.09 / 10.72
//   R9:  3344 x 256, no-pred    -> 6.82 / 6.59  <- this kernel
//   R11: 6688 x 128             -> 7.62 / 8.96
//   R13-R16: identical binary   -> ncu {7.07, 6.85, 6.98, 8.35}
//                                  wall {8.51, 6.59, 6.66, 8.67}
// Five same-binary runs establish the session band; R16's slow sample has
// the slow-DVFS signature (DRAM% down, issue% up, same stream) — capture is
// --clock-control none, so session clock varies. Kernel is at its measured
// floor (ramp/first-touch latency bound). Holding the optimum:
// 3344 x 256, one unpredicated float4 per thread.
// N4 = 856,064 = 3344 * 256 exactly -> no predicate, no tail.

__global__ void __launch_bounds__(256)
cspn_copy_kernel(const float4* __restrict__ in,
                 float4* __restrict__ out) {
    int i = blockIdx.x * 256 + threadIdx.x;
    out[i] = in[i];
}

extern "C" void kernel_launch(void* const* d_in, const int* in_sizes, int n_in,
                              void* d_out, int out_size) {
    // Inputs (metadata order): guidance, blur_depth, sparse_depth, sum_w
    const float* blur_depth = (const float*)d_in[1];
    float* out = (float*)d_out;

    int n  = in_sizes[1];      // 3,424,256
    int n4 = n >> 2;           // 856,064 float4 = 3344 * 256 exactly
    int blocks = n4 >> 8;      // 3344 (exact; no tail)

    cspn_copy_kernel<<<blocks, 256>>>((const float4*)blur_depth, (float4*)out);
}